// round 13
// baseline (speedup 1.0000x reference)
#include <cuda_runtime.h>
#include <cuda_fp16.h>
#include <math.h>

#define N_CAPS 64
#define IN_CAPS 4096
#define CAP_DIM 32
#define IN_DIM 16
#define EPS 1e-7f

#define RGRID 128                // routing blocks; co-resident (1 block/SM)
#define RTPB 1024
#define NWARP 32
#define PPB (N_CAPS * IN_CAPS / RGRID)  // 2048 pairs per routing block
#define PPW (PPB / NWARP)               // 64 pairs per warp (staging only)
#define UROW 2050                       // padded words per k-row (bank-conflict-free)
#define SMEM_U_BYTES (16 * UROW * 4)    // 131200 B

// globals (allocation-free rule)
__device__ __half g_u16[(size_t)N_CAPS * IN_CAPS * CAP_DIM];  // 16.75 MB fp16 u
__device__ float g_ps[RGRID][CAP_DIM];    // per-block partial S
__device__ float g_pz[RGRID];             // per-block partial Z
__device__ float g_v[N_CAPS * CAP_DIM];   // cumulative v
__device__ unsigned int g_cnt[3] = {0u, 0u, 0u};
__device__ unsigned int g_flag[2] = {0u, 0u};

// ---------------------------------------------------------------------------
// u[n,i,d] = sum_k W[n,i,d,k] * x[i,k]
// Standalone HBM-streaming config (~7 TB/s measured): one warp per (n,i),
// lane = d, 256 tpb, huge grid, no smem. Output fp16 pair-major.
// ---------------------------------------------------------------------------
__global__ __launch_bounds__(256) void uhat_kernel(const float* __restrict__ W,
                                                   const float* __restrict__ x) {
    int w = blockIdx.x * 8 + (threadIdx.x >> 5);   // global pair index
    int lane = threadIdx.x & 31;                   // d
    int i = w & (IN_CAPS - 1);

    const float4* xp = reinterpret_cast<const float4*>(x + (size_t)i * IN_DIM);
    float4 x0 = xp[0], x1 = xp[1], x2 = xp[2], x3 = xp[3];

    const float4* wp = reinterpret_cast<const float4*>(
        W + ((size_t)w * CAP_DIM + lane) * IN_DIM);
    float4 w0 = wp[0], w1 = wp[1], w2 = wp[2], w3 = wp[3];

    float acc = w0.x * x0.x + w0.y * x0.y + w0.z * x0.z + w0.w * x0.w;
    acc      += w1.x * x1.x + w1.y * x1.y + w1.z * x1.z + w1.w * x1.w;
    acc      += w2.x * x2.x + w2.y * x2.y + w2.z * x2.z + w2.w * x2.w;
    acc      += w3.x * x3.x + w3.y * x3.y + w3.z * x3.z + w3.w * x3.w;

    g_u16[(size_t)w * CAP_DIM + lane] = __float2half_rn(acc);
}

// ---------------------------------------------------------------------------
// Persistent routing kernel.
// Iter 0 (e==1): global->SMEM staging of u, TRANSPOSED k-major with UROW pad
//   (u_sm[k*UROW + p] = half2 word k of pair p) + exact fp32 partial S.
// Iters 1-2: per-thread whole pairs, everything in registers, NO shuffles in
//   the hot loop; one 31-shfl exchange-halving warp reduce per iteration.
// ---------------------------------------------------------------------------
__global__ void __launch_bounds__(RTPB, 1)
route_kernel(float* __restrict__ out)
{
    extern __shared__ unsigned int u_sm[];
    const int tid  = threadIdx.x;
    const int wid  = tid >> 5;
    const int lane = tid & 31;
    const int blk  = blockIdx.x;
    const int n    = blk >> 1;

    const unsigned int* __restrict__ u32 =
        reinterpret_cast<const unsigned int*>(g_u16) + (size_t)blk * PPB * 16;

    __shared__ float2 sm_B[NWARP][CAP_DIM];        // iter0 reduce
    __shared__ float  sm_E[NWARP][CAP_DIM];        // iter1-2 reduce
    __shared__ float  sm_z[NWARP];
    __shared__ float  sm_red[NWARP];
    __shared__ float  sm_scale;
    __shared__ unsigned int sm_last;

    for (int t = 0; t < 3; t++) {
        if (t == 0) {
            // ---- staging pass: copy u (transposed) + iter0 partial (e == 1) ----
            const int l16 = lane & 15;
            float ax = 0.f, ay = 0.f;
            const int pbase = wid * PPW + (lane >> 4);
#pragma unroll 4
            for (int s2 = 0; s2 < PPW / 2; s2++) {
                const int p = pbase + 2 * s2;
                unsigned int wrd = u32[p * 16 + l16];          // coalesced 128B/warp
                u_sm[l16 * UROW + p] = wrd;                    // conflict-free STS
                __half2 h = *reinterpret_cast<__half2*>(&wrd);
                float2 uu = __half22float2(h);
                ax += uu.x; ay += uu.y;
            }
            sm_B[wid][lane] = make_float2(ax, ay);
            __syncthreads();
            if (tid < CAP_DIM) {
                const int k = tid >> 1, j = tid & 1;
                float s = 0.f;
#pragma unroll
                for (int w2 = 0; w2 < NWARP; w2++) {
                    float2 a  = sm_B[w2][k];
                    float2 b2 = sm_B[w2][k + 16];
                    s += j ? (a.y + b2.y) : (a.x + b2.x);
                }
                g_ps[blk][tid] = s;
            }
        } else {
            // ---- per-thread pair scan, register-resident, shuffle-free ----
            float vv[CAP_DIM];
            {
                const float4* vp = reinterpret_cast<const float4*>(&g_v[n * CAP_DIM]);
#pragma unroll
                for (int j = 0; j < 8; j++) {
                    float4 q = __ldg(vp + j);
                    vv[4 * j + 0] = q.x; vv[4 * j + 1] = q.y;
                    vv[4 * j + 2] = q.z; vv[4 * j + 3] = q.w;
                }
            }
            float A[CAP_DIM];
#pragma unroll
            for (int d = 0; d < CAP_DIM; d++) A[d] = 0.f;
            float zacc = 0.f;

#pragma unroll
            for (int r = 0; r < PPB / RTPB; r++) {             // 2 pairs per thread
                const int p = tid + r * RTPB;
                float uf[CAP_DIM];
#pragma unroll
                for (int k = 0; k < 16; k++) {                 // conflict-free LDS
                    unsigned int wrd = u_sm[k * UROW + p];
                    __half2 h = *reinterpret_cast<__half2*>(&wrd);
                    float2 f = __half22float2(h);
                    uf[2 * k] = f.x; uf[2 * k + 1] = f.y;
                }
                float dt = 0.f;
#pragma unroll
                for (int d = 0; d < CAP_DIM; d++) dt += uf[d] * vv[d];
                float e = __expf(dt);
                zacc += e;
#pragma unroll
                for (int d = 0; d < CAP_DIM; d++) A[d] += e * uf[d];
            }

            // exchange-halving warp reduce: lane l ends with S[d==l] (31 shfls)
#pragma unroll
            for (int m = 16; m >= 1; m >>= 1) {
                const bool hi = (lane & m) != 0;
#pragma unroll
                for (int q = 0; q < m; q++) {
                    float send = hi ? A[q] : A[q + m];
                    float recv = __shfl_xor_sync(0xffffffffu, send, m);
                    A[q] = (hi ? A[q + m] : A[q]) + recv;
                }
            }
#pragma unroll
            for (int o = 16; o > 0; o >>= 1)
                zacc += __shfl_xor_sync(0xffffffffu, zacc, o);
            sm_E[wid][lane] = A[0];
            if (lane == 0) sm_z[wid] = zacc;
            __syncthreads();
            if (tid < CAP_DIM) {
                float s = 0.f;
#pragma unroll
                for (int w2 = 0; w2 < NWARP; w2++) s += sm_E[w2][tid];
                g_ps[blk][tid] = s;
            } else if (tid == CAP_DIM) {
                float zt = 0.f;
#pragma unroll
                for (int w2 = 0; w2 < NWARP; w2++) zt += sm_z[w2];
                g_pz[blk] = zt;
            }
        }

        // ---- arrive ----
        __threadfence();
        __syncthreads();
        if (tid == 0) {
            unsigned int prev = atomicAdd(&g_cnt[t], 1u);
            sm_last = (prev == RGRID - 1) ? 1u : 0u;
        }
        __syncthreads();

        if (sm_last) {
            // ---- combine (deterministic fixed-order reduction) ----
            __threadfence();
            float sr[2]; float sq = 0.f;
#pragma unroll
            for (int r = 0; r < 2; r++) {
                int idx = tid + r * RTPB;        // idx = n2*32 + d  (2048 total)
                int n2 = idx >> 5, d = idx & 31;
                float num = g_ps[2 * n2][d] + g_ps[2 * n2 + 1][d];
                float Z = (t == 0) ? (float)IN_CAPS : (g_pz[2 * n2] + g_pz[2 * n2 + 1]);
                float s = num / Z;
                sr[r] = s; sq += s * s;
            }
#pragma unroll
            for (int o = 16; o > 0; o >>= 1) sq += __shfl_xor_sync(0xffffffffu, sq, o);
            if (lane == 0) sm_red[wid] = sq;
            __syncthreads();
            if (tid == 0) {
                float tt = 0.f;
#pragma unroll
                for (int k = 0; k < NWARP; k++) tt += sm_red[k];
                sm_scale = tt / (1.0f + tt) / (sqrtf(tt) + EPS);
            }
            __syncthreads();
            const float scale = sm_scale;
#pragma unroll
            for (int r = 0; r < 2; r++) {
                int idx = tid + r * RTPB;
                float v = sr[r] * scale;
                if (t == 0)      g_v[idx] = v;       // overwrite: replay-safe init
                else if (t == 1) g_v[idx] += v;      // cumulative for iter 2
                else             out[idx] = v;       // final output
            }
            __threadfence();
            __syncthreads();
            if (tid == 0) {
                if (t < 2) {
                    atomicExch(&g_flag[t], 1u);      // release
                } else {
                    g_cnt[0] = 0u; g_cnt[1] = 0u; g_cnt[2] = 0u;   // replay reset
                    g_flag[0] = 0u; g_flag[1] = 0u;
                }
            }
        } else {
            if (t == 2) return;                      // partials written; done
            if (tid == 0) {
                while (atomicAdd(&g_flag[t], 0u) == 0u) __nanosleep(64);
            }
            __syncthreads();
            __threadfence();
        }
    }
}

// ---------------------------------------------------------------------------
extern "C" void kernel_launch(void* const* d_in, const int* in_sizes, int n_in,
                              void* d_out, int out_size) {
    const float* x = (const float*)d_in[0];
    const float* W = (const float*)d_in[1];
    if (in_sizes[0] > in_sizes[1]) { const float* t = x; x = W; W = t; }
    float* out = (float*)d_out;

    const int pairs = N_CAPS * IN_CAPS;          // 262144
    uhat_kernel<<<pairs / 8, 256>>>(W, x);       // HBM-streaming u = W.x

    cudaFuncSetAttribute(route_kernel,
                         cudaFuncAttributeMaxDynamicSharedMemorySize, SMEM_U_BYTES);
    route_kernel<<<RGRID, RTPB, SMEM_U_BYTES>>>(out);
}

// round 14
// speedup vs baseline: 1.0069x; 1.0069x over previous
#include <cuda_runtime.h>
#include <cuda_fp16.h>
#include <math.h>

#define N_CAPS 64
#define IN_CAPS 4096
#define CAP_DIM 32
#define IN_DIM 16
#define EPS 1e-7f

#define RGRID 128                // routing blocks; co-resident (1 block/SM)
#define RTPB 512                 // 512 threads -> 128-reg budget (NO spills)
#define NWARP 16
#define PPB (N_CAPS * IN_CAPS / RGRID)  // 2048 pairs per routing block
#define PPW (PPB / NWARP)               // 128 pairs per warp (staging)
#define PPT (PPB / RTPB)                // 4 pairs per thread (scan)
#define UROW 2050                       // padded words per k-row (conflict-free)
#define SMEM_U_BYTES (16 * UROW * 4)    // 131200 B

// globals (allocation-free rule)
__device__ __half g_u16[(size_t)N_CAPS * IN_CAPS * CAP_DIM];  // 16.75 MB fp16 u
__device__ float g_ps[RGRID][CAP_DIM];    // per-block partial S
__device__ float g_pz[RGRID];             // per-block partial Z
__device__ float g_v[N_CAPS * CAP_DIM];   // cumulative v
__device__ unsigned int g_cnt[3] = {0u, 0u, 0u};
__device__ unsigned int g_flag[2] = {0u, 0u};

// ---------------------------------------------------------------------------
// u[n,i,d] = sum_k W[n,i,d,k] * x[i,k]
// Standalone HBM-streaming config (~7 TB/s measured): one warp per (n,i),
// lane = d, 256 tpb, huge grid, no smem. Output fp16 pair-major.
// ---------------------------------------------------------------------------
__global__ __launch_bounds__(256) void uhat_kernel(const float* __restrict__ W,
                                                   const float* __restrict__ x) {
    int w = blockIdx.x * 8 + (threadIdx.x >> 5);   // global pair index
    int lane = threadIdx.x & 31;                   // d
    int i = w & (IN_CAPS - 1);

    const float4* xp = reinterpret_cast<const float4*>(x + (size_t)i * IN_DIM);
    float4 x0 = xp[0], x1 = xp[1], x2 = xp[2], x3 = xp[3];

    const float4* wp = reinterpret_cast<const float4*>(
        W + ((size_t)w * CAP_DIM + lane) * IN_DIM);
    float4 w0 = wp[0], w1 = wp[1], w2 = wp[2], w3 = wp[3];

    float acc = w0.x * x0.x + w0.y * x0.y + w0.z * x0.z + w0.w * x0.w;
    acc      += w1.x * x1.x + w1.y * x1.y + w1.z * x1.z + w1.w * x1.w;
    acc      += w2.x * x2.x + w2.y * x2.y + w2.z * x2.z + w2.w * x2.w;
    acc      += w3.x * x3.x + w3.y * x3.y + w3.z * x3.z + w3.w * x3.w;

    g_u16[(size_t)w * CAP_DIM + lane] = __float2half_rn(acc);
}

// ---------------------------------------------------------------------------
// Persistent routing kernel (512 threads -> 128 regs, no spills).
// Iter 0: global->SMEM staging of u, TRANSPOSED k-major (u_sm[k*UROW+p]) +
//         exact fp32 partial S (e == 1).
// Iters 1-2: 4 whole pairs per thread, register-resident, shuffle-free hot
//         loop; one 31-shfl exchange-halving warp reduce per iteration.
// ---------------------------------------------------------------------------
__global__ void __launch_bounds__(RTPB, 1)
route_kernel(float* __restrict__ out)
{
    extern __shared__ unsigned int u_sm[];
    const int tid  = threadIdx.x;
    const int wid  = tid >> 5;
    const int lane = tid & 31;
    const int blk  = blockIdx.x;
    const int n    = blk >> 1;

    const unsigned int* __restrict__ u32 =
        reinterpret_cast<const unsigned int*>(g_u16) + (size_t)blk * PPB * 16;

    __shared__ float2 sm_B[NWARP][CAP_DIM];        // iter0 reduce
    __shared__ float  sm_E[NWARP][CAP_DIM];        // iter1-2 reduce
    __shared__ float  sm_z[NWARP];
    __shared__ float  sm_red[NWARP];
    __shared__ float  sm_scale;
    __shared__ unsigned int sm_last;

    for (int t = 0; t < 3; t++) {
        if (t == 0) {
            // ---- staging: coalesced copy of u (transposed) + iter0 partial ----
            const int l16 = lane & 15;
            float ax = 0.f, ay = 0.f;
            const int pbase = wid * PPW + (lane >> 4);
#pragma unroll 4
            for (int s2 = 0; s2 < PPW / 2; s2++) {
                const int p = pbase + 2 * s2;
                unsigned int wrd = u32[p * 16 + l16];          // 128B per warp
                u_sm[l16 * UROW + p] = wrd;                    // conflict-free STS
                __half2 h = *reinterpret_cast<__half2*>(&wrd);
                float2 uu = __half22float2(h);
                ax += uu.x; ay += uu.y;
            }
            sm_B[wid][lane] = make_float2(ax, ay);
            __syncthreads();
            if (tid < CAP_DIM) {
                const int k = tid >> 1, j = tid & 1;
                float s = 0.f;
#pragma unroll
                for (int w2 = 0; w2 < NWARP; w2++) {
                    float2 a  = sm_B[w2][k];
                    float2 b2 = sm_B[w2][k + 16];
                    s += j ? (a.y + b2.y) : (a.x + b2.x);
                }
                g_ps[blk][tid] = s;
            }
        } else {
            // ---- per-thread pair scan, register-resident, shuffle-free ----
            float vv[CAP_DIM];
            {
                const float4* vp = reinterpret_cast<const float4*>(&g_v[n * CAP_DIM]);
#pragma unroll
                for (int j = 0; j < 8; j++) {
                    float4 q = __ldg(vp + j);
                    vv[4 * j + 0] = q.x; vv[4 * j + 1] = q.y;
                    vv[4 * j + 2] = q.z; vv[4 * j + 3] = q.w;
                }
            }
            float A[CAP_DIM];
#pragma unroll
            for (int d = 0; d < CAP_DIM; d++) A[d] = 0.f;
            float zacc = 0.f;

#pragma unroll
            for (int r = 0; r < PPT; r++) {                    // 4 pairs per thread
                const int p = tid + r * RTPB;
                float uf[CAP_DIM];
#pragma unroll
                for (int k = 0; k < 16; k++) {                 // conflict-free LDS
                    unsigned int wrd = u_sm[k * UROW + p];
                    __half2 h = *reinterpret_cast<__half2*>(&wrd);
                    float2 f = __half22float2(h);
                    uf[2 * k] = f.x; uf[2 * k + 1] = f.y;
                }
                float dt = 0.f;
#pragma unroll
                for (int d = 0; d < CAP_DIM; d++) dt += uf[d] * vv[d];
                float e = __expf(dt);
                zacc += e;
#pragma unroll
                for (int d = 0; d < CAP_DIM; d++) A[d] += e * uf[d];
            }

            // exchange-halving warp reduce: lane l ends with S[d==l] (31 shfls)
#pragma unroll
            for (int m = 16; m >= 1; m >>= 1) {
                const bool hi = (lane & m) != 0;
#pragma unroll
                for (int q = 0; q < m; q++) {
                    float send = hi ? A[q] : A[q + m];
                    float recv = __shfl_xor_sync(0xffffffffu, send, m);
                    A[q] = (hi ? A[q + m] : A[q]) + recv;
                }
            }
#pragma unroll
            for (int o = 16; o > 0; o >>= 1)
                zacc += __shfl_xor_sync(0xffffffffu, zacc, o);
            sm_E[wid][lane] = A[0];
            if (lane == 0) sm_z[wid] = zacc;
            __syncthreads();
            if (tid < CAP_DIM) {
                float s = 0.f;
#pragma unroll
                for (int w2 = 0; w2 < NWARP; w2++) s += sm_E[w2][tid];
                g_ps[blk][tid] = s;
            } else if (tid == CAP_DIM) {
                float zt = 0.f;
#pragma unroll
                for (int w2 = 0; w2 < NWARP; w2++) zt += sm_z[w2];
                g_pz[blk] = zt;
            }
        }

        // ---- arrive ----
        __threadfence();
        __syncthreads();
        if (tid == 0) {
            unsigned int prev = atomicAdd(&g_cnt[t], 1u);
            sm_last = (prev == RGRID - 1) ? 1u : 0u;
        }
        __syncthreads();

        if (sm_last) {
            // ---- combine (deterministic fixed-order reduction) ----
            __threadfence();
            float sr[4]; float sq = 0.f;
#pragma unroll
            for (int r = 0; r < 4; r++) {
                int idx = tid + r * RTPB;        // idx = n2*32 + d  (2048 total)
                int n2 = idx >> 5, d = idx & 31;
                float num = g_ps[2 * n2][d] + g_ps[2 * n2 + 1][d];
                float Z = (t == 0) ? (float)IN_CAPS : (g_pz[2 * n2] + g_pz[2 * n2 + 1]);
                float s = num / Z;
                sr[r] = s; sq += s * s;
            }
#pragma unroll
            for (int o = 16; o > 0; o >>= 1) sq += __shfl_xor_sync(0xffffffffu, sq, o);
            if (lane == 0) sm_red[wid] = sq;
            __syncthreads();
            if (tid == 0) {
                float tt = 0.f;
#pragma unroll
                for (int k = 0; k < NWARP; k++) tt += sm_red[k];
                sm_scale = tt / (1.0f + tt) / (sqrtf(tt) + EPS);
            }
            __syncthreads();
            const float scale = sm_scale;
#pragma unroll
            for (int r = 0; r < 4; r++) {
                int idx = tid + r * RTPB;
                float v = sr[r] * scale;
                if (t == 0)      g_v[idx] = v;       // overwrite: replay-safe init
                else if (t == 1) g_v[idx] += v;      // cumulative for iter 2
                else             out[idx] = v;       // final output
            }
            __threadfence();
            __syncthreads();
            if (tid == 0) {
                if (t < 2) {
                    atomicExch(&g_flag[t], 1u);      // release
                } else {
                    g_cnt[0] = 0u; g_cnt[1] = 0u; g_cnt[2] = 0u;   // replay reset
                    g_flag[0] = 0u; g_flag[1] = 0u;
                }
            }
        } else {
            if (t == 2) return;                      // partials written; done
            if (tid == 0) {
                while (atomicAdd(&g_flag[t], 0u) == 0u) __nanosleep(64);
            }
            __syncthreads();
            __threadfence();
        }
    }
}

// ---------------------------------------------------------------------------
extern "C" void kernel_launch(void* const* d_in, const int* in_sizes, int n_in,
                              void* d_out, int out_size) {
    const float* x = (const float*)d_in[0];
    const float* W = (const float*)d_in[1];
    if (in_sizes[0] > in_sizes[1]) { const float* t = x; x = W; W = t; }
    float* out = (float*)d_out;

    const int pairs = N_CAPS * IN_CAPS;          // 262144
    uhat_kernel<<<pairs / 8, 256>>>(W, x);       // HBM-streaming u = W.x

    cudaFuncSetAttribute(route_kernel,
                         cudaFuncAttributeMaxDynamicSharedMemorySize, SMEM_U_BYTES);
    route_kernel<<<RGRID, RTPB, SMEM_U_BYTES>>>(out);
}

// round 15
// speedup vs baseline: 1.1156x; 1.1079x over previous
#include <cuda_runtime.h>
#include <cuda_fp16.h>
#include <math.h>

#define N_CAPS 64
#define IN_CAPS 4096
#define CAP_DIM 32
#define IN_DIM 16
#define EPS 1e-7f

#define RGRID 128                // routing blocks; co-resident (1 block/SM)
#define RTPB 512                 // 512 threads -> 128-reg budget
#define NWARP 16
#define PPB (N_CAPS * IN_CAPS / RGRID)  // 2048 pairs per routing block
#define PPT (PPB / RTPB)                // 4 pairs per thread (scan)
#define UROW 2050                       // padded words per k-row (conflict-free)
#define SMEM_U_BYTES (16 * UROW * 4)    // 131200 B

// globals (allocation-free rule)
__device__ __half g_u16[(size_t)N_CAPS * IN_CAPS * CAP_DIM];  // 16.75 MB fp16 u
__device__ float g_ps[RGRID][CAP_DIM];    // per-block partial S
__device__ float g_pz[RGRID];             // per-block partial Z
__device__ float g_v[N_CAPS * CAP_DIM];   // cumulative v
__device__ unsigned int g_cnt[3] = {0u, 0u, 0u};
__device__ unsigned int g_flag[2] = {0u, 0u};

// ---------------------------------------------------------------------------
// u[n,i,d] = sum_k W[n,i,d,k] * x[i,k]
// Standalone HBM-streaming config (~7 TB/s measured): one warp per (n,i),
// lane = d, 256 tpb, huge grid, no smem. W read with __ldcs (evict-first)
// so the 536MB stream does NOT evict the 16.75MB u writes from L2 — the
// routing kernel then stages u from L2, not DRAM.
// ---------------------------------------------------------------------------
__global__ __launch_bounds__(256) void uhat_kernel(const float* __restrict__ W,
                                                   const float* __restrict__ x) {
    int w = blockIdx.x * 8 + (threadIdx.x >> 5);   // global pair index
    int lane = threadIdx.x & 31;                   // d
    int i = w & (IN_CAPS - 1);

    const float4* xp = reinterpret_cast<const float4*>(x + (size_t)i * IN_DIM);
    float4 x0 = __ldg(xp), x1 = __ldg(xp + 1), x2 = __ldg(xp + 2), x3 = __ldg(xp + 3);

    const float4* wp = reinterpret_cast<const float4*>(
        W + ((size_t)w * CAP_DIM + lane) * IN_DIM);
    float4 w0 = __ldcs(wp), w1 = __ldcs(wp + 1), w2 = __ldcs(wp + 2), w3 = __ldcs(wp + 3);

    float acc = w0.x * x0.x + w0.y * x0.y + w0.z * x0.z + w0.w * x0.w;
    acc      += w1.x * x1.x + w1.y * x1.y + w1.z * x1.z + w1.w * x1.w;
    acc      += w2.x * x2.x + w2.y * x2.y + w2.z * x2.z + w2.w * x2.w;
    acc      += w3.x * x3.x + w3.y * x3.y + w3.z * x3.z + w3.w * x3.w;

    g_u16[(size_t)w * CAP_DIM + lane] = __float2half_rn(acc);
}

// ---------------------------------------------------------------------------
// Persistent routing kernel (512 threads, 1 block/SM).
// Iter 0: BATCH-LOADED staging — each thread front-loads 16 independent
//   uint4 (256B coalesced; ~64 lines in flight per warp -> latency-immune),
//   then transpose-stores to k-major smem (u_sm[k*UROW+p], conflict-free:
//   bank=(2k+p)%32 covers all 32) and accumulates the iter-0 partial
//   (thread owns fixed dims 8*(tid&3)..+8 across its 16 pairs).
// Iters 1-2: 4 whole pairs per thread, register-resident, shuffle-free.
// ---------------------------------------------------------------------------
__global__ void __launch_bounds__(RTPB, 1)
route_kernel(float* __restrict__ out)
{
    extern __shared__ unsigned int u_sm[];
    const int tid  = threadIdx.x;
    const int wid  = tid >> 5;
    const int lane = tid & 31;
    const int blk  = blockIdx.x;
    const int n    = blk >> 1;

    __shared__ float  sm_E[NWARP][CAP_DIM];
    __shared__ float  sm_z[NWARP];
    __shared__ float  sm_red[NWARP];
    __shared__ float  sm_scale;
    __shared__ unsigned int sm_last;

    for (int t = 0; t < 3; t++) {
        if (t == 0) {
            // ---- batch-load staging + iter0 partial (e == 1) ----
            const uint4* gsrc = reinterpret_cast<const uint4*>(g_u16)
                                + (size_t)blk * (PPB * 16 / 4);   // 8192 uint4/block
            uint4 buf[16];
#pragma unroll
            for (int r = 0; r < 16; r++)
                buf[r] = __ldg(gsrc + tid + r * RTPB);            // 16 indep LDG.128

            const int k0 = (tid & 3) * 4;      // this thread's word base (fixed)
            const int pb = tid >> 2;           // pair base; pair = pb + 128*r
            float A8[8];
#pragma unroll
            for (int j = 0; j < 8; j++) A8[j] = 0.f;

#pragma unroll
            for (int r = 0; r < 16; r++) {
                const int p = pb + 128 * r;
                u_sm[(k0 + 0) * UROW + p] = buf[r].x;
                u_sm[(k0 + 1) * UROW + p] = buf[r].y;
                u_sm[(k0 + 2) * UROW + p] = buf[r].z;
                u_sm[(k0 + 3) * UROW + p] = buf[r].w;
                __half2 h0 = *reinterpret_cast<__half2*>(&buf[r].x);
                __half2 h1 = *reinterpret_cast<__half2*>(&buf[r].y);
                __half2 h2 = *reinterpret_cast<__half2*>(&buf[r].z);
                __half2 h3 = *reinterpret_cast<__half2*>(&buf[r].w);
                float2 f0 = __half22float2(h0), f1 = __half22float2(h1);
                float2 f2 = __half22float2(h2), f3 = __half22float2(h3);
                A8[0] += f0.x; A8[1] += f0.y; A8[2] += f1.x; A8[3] += f1.y;
                A8[4] += f2.x; A8[5] += f2.y; A8[6] += f3.x; A8[7] += f3.y;
            }
            // lanes sharing (lane&3) hold same dims over disjoint pairs
#pragma unroll
            for (int o = 4; o <= 16; o <<= 1) {
#pragma unroll
                for (int j = 0; j < 8; j++)
                    A8[j] += __shfl_xor_sync(0xffffffffu, A8[j], o);
            }
            if (lane < 4) {
#pragma unroll
                for (int j = 0; j < 8; j++)
                    sm_E[wid][8 * lane + j] = A8[j];   // dims 8*(lane)..+8
            }
            __syncthreads();
            if (tid < CAP_DIM) {
                float s = 0.f;
#pragma unroll
                for (int w2 = 0; w2 < NWARP; w2++) s += sm_E[w2][tid];
                g_ps[blk][tid] = s;
            }
        } else {
            // ---- per-thread pair scan, register-resident, shuffle-free ----
            float vv[CAP_DIM];
            {
                const float4* vp = reinterpret_cast<const float4*>(&g_v[n * CAP_DIM]);
#pragma unroll
                for (int j = 0; j < 8; j++) {
                    float4 q = __ldg(vp + j);
                    vv[4 * j + 0] = q.x; vv[4 * j + 1] = q.y;
                    vv[4 * j + 2] = q.z; vv[4 * j + 3] = q.w;
                }
            }
            float A[CAP_DIM];
#pragma unroll
            for (int d = 0; d < CAP_DIM; d++) A[d] = 0.f;
            float zacc = 0.f;

#pragma unroll
            for (int r = 0; r < PPT; r++) {                    // 4 pairs per thread
                const int p = tid + r * RTPB;
                float uf[CAP_DIM];
#pragma unroll
                for (int k = 0; k < 16; k++) {                 // conflict-free LDS
                    unsigned int wrd = u_sm[k * UROW + p];
                    __half2 h = *reinterpret_cast<__half2*>(&wrd);
                    float2 f = __half22float2(h);
                    uf[2 * k] = f.x; uf[2 * k + 1] = f.y;
                }
                float dt = 0.f;
#pragma unroll
                for (int d = 0; d < CAP_DIM; d++) dt += uf[d] * vv[d];
                float e = __expf(dt);
                zacc += e;
#pragma unroll
                for (int d = 0; d < CAP_DIM; d++) A[d] += e * uf[d];
            }

            // exchange-halving warp reduce: lane l ends with S[d==l] (31 shfls)
#pragma unroll
            for (int m = 16; m >= 1; m >>= 1) {
                const bool hi = (lane & m) != 0;
#pragma unroll
                for (int q = 0; q < m; q++) {
                    float send = hi ? A[q] : A[q + m];
                    float recv = __shfl_xor_sync(0xffffffffu, send, m);
                    A[q] = (hi ? A[q + m] : A[q]) + recv;
                }
            }
#pragma unroll
            for (int o = 16; o > 0; o >>= 1)
                zacc += __shfl_xor_sync(0xffffffffu, zacc, o);
            sm_E[wid][lane] = A[0];
            if (lane == 0) sm_z[wid] = zacc;
            __syncthreads();
            if (tid < CAP_DIM) {
                float s = 0.f;
#pragma unroll
                for (int w2 = 0; w2 < NWARP; w2++) s += sm_E[w2][tid];
                g_ps[blk][tid] = s;
            } else if (tid == CAP_DIM) {
                float zt = 0.f;
#pragma unroll
                for (int w2 = 0; w2 < NWARP; w2++) zt += sm_z[w2];
                g_pz[blk] = zt;
            }
        }

        // ---- arrive ----
        __threadfence();
        __syncthreads();
        if (tid == 0) {
            unsigned int prev = atomicAdd(&g_cnt[t], 1u);
            sm_last = (prev == RGRID - 1) ? 1u : 0u;
        }
        __syncthreads();

        if (sm_last) {
            // ---- combine (deterministic fixed-order reduction) ----
            __threadfence();
            float sr[4]; float sq = 0.f;
#pragma unroll
            for (int r = 0; r < 4; r++) {
                int idx = tid + r * RTPB;        // idx = n2*32 + d  (2048 total)
                int n2 = idx >> 5, d = idx & 31;
                float num = g_ps[2 * n2][d] + g_ps[2 * n2 + 1][d];
                float Z = (t == 0) ? (float)IN_CAPS : (g_pz[2 * n2] + g_pz[2 * n2 + 1]);
                float s = num / Z;
                sr[r] = s; sq += s * s;
            }
#pragma unroll
            for (int o = 16; o > 0; o >>= 1) sq += __shfl_xor_sync(0xffffffffu, sq, o);
            if (lane == 0) sm_red[wid] = sq;
            __syncthreads();
            if (tid == 0) {
                float tt = 0.f;
#pragma unroll
                for (int k = 0; k < NWARP; k++) tt += sm_red[k];
                sm_scale = tt / (1.0f + tt) / (sqrtf(tt) + EPS);
            }
            __syncthreads();
            const float scale = sm_scale;
#pragma unroll
            for (int r = 0; r < 4; r++) {
                int idx = tid + r * RTPB;
                float v = sr[r] * scale;
                if (t == 0)      g_v[idx] = v;       // overwrite: replay-safe init
                else if (t == 1) g_v[idx] += v;      // cumulative for iter 2
                else             out[idx] = v;       // final output
            }
            __threadfence();
            __syncthreads();
            if (tid == 0) {
                if (t < 2) {
                    atomicExch(&g_flag[t], 1u);      // release
                } else {
                    g_cnt[0] = 0u; g_cnt[1] = 0u; g_cnt[2] = 0u;   // replay reset
                    g_flag[0] = 0u; g_flag[1] = 0u;
                }
            }
        } else {
            if (t == 2) return;                      // partials written; done
            if (tid == 0) {
                while (atomicAdd(&g_flag[t], 0u) == 0u) __nanosleep(64);
            }
            __syncthreads();
            __threadfence();
        }
    }
}

// ---------------------------------------------------------------------------
extern "C" void kernel_launch(void* const* d_in, const int* in_sizes, int n_in,
                              void* d_out, int out_size) {
    const float* x = (const float*)d_in[0];
    const float* W = (const float*)d_in[1];
    if (in_sizes[0] > in_sizes[1]) { const float* t = x; x = W; W = t; }
    float* out = (float*)d_out;

    const int pairs = N_CAPS * IN_CAPS;          // 262144
    uhat_kernel<<<pairs / 8, 256>>>(W, x);       // HBM-streaming u = W.x

    cudaFuncSetAttribute(route_kernel,
                         cudaFuncAttributeMaxDynamicSharedMemorySize, SMEM_U_BYTES);
    route_kernel<<<RGRID, RTPB, SMEM_U_BYTES>>>(out);
}